// round 6
// baseline (speedup 1.0000x reference)
#include <cuda_runtime.h>
#include <cstdint>

// LTC scan, round 6.
// R5 post-mortem: fma-pipe busy (~727us) is at the fp32 FMA roofline for this
// op count; wall = 2.1x pipe-busy because all 8 warps share one barrier domain
// (issue 42%). R6: rows 0-1 (warps 0-3) and rows 2-3 (warps 4-7) are fully
// independent -> split them into separate named-barrier domains so one group's
// FFMA2 burst hides the other's f2sum/STS/BAR/tanh tail.
// Also: xin_kernel launch_bounds (128,3)->(128,2) (was register-capped ->
// probable local spills).

#define Bsz 512
#define Ssz 512
#define Dsz 128
#define Hsz 128
#define UNFOLDS 6

__device__ float g_xin[(size_t)Bsz * Ssz * Hsz];   // [b][s][h] scratch

__device__ __forceinline__ unsigned long long ffma2(unsigned long long a,
                                                    unsigned long long b,
                                                    unsigned long long c) {
    unsigned long long d;
    asm("fma.rn.f32x2 %0, %1, %2, %3;" : "=l"(d) : "l"(a), "l"(b), "l"(c));
    return d;
}

__device__ __forceinline__ float f2sum(unsigned long long v) {
    float lo, hi;
    asm("mov.b64 {%0, %1}, %2;" : "=f"(lo), "=f"(hi) : "l"(v));
    return lo + hi;
}

__device__ __forceinline__ float ftanh(float s) {
    float e = __expf(2.0f * s);
    return 1.0f - __fdividef(2.0f, e + 1.0f);
}

__device__ __forceinline__ void group_bar(int id) {
    asm volatile("bar.sync %0, 128;" :: "r"(id) : "memory");
}

// ---------------------------------------------------------------------------
// Kernel 1: xin[b,s,j] = sum_d x[b,s,d] * W_in[j,d] + b_in[j]
// ---------------------------------------------------------------------------
__global__ void __launch_bounds__(128, 2)
xin_kernel(const float* __restrict__ x,
           const float* __restrict__ W_in,
           const float* __restrict__ b_in)
{
    __shared__ float xs[2][4 * Dsz];

    const int j = threadIdx.x;

    unsigned long long wi[64];
    {
        const ulonglong2* wp = (const ulonglong2*)(W_in + j * Dsz);
        #pragma unroll
        for (int c = 0; c < 32; ++c) {
            ulonglong2 v = wp[c];
            wi[2 * c]     = v.x;
            wi[2 * c + 1] = v.y;
        }
    }
    const float bi = b_in[j];

    const int m0 = blockIdx.x * 128;

    float xf[4];
    #pragma unroll
    for (int r = 0; r < 4; ++r)
        xf[r] = x[(size_t)(m0 + r) * Dsz + j];

    #pragma unroll 1
    for (int ch = 0; ch < 32; ++ch) {
        float* xb = xs[ch & 1];
        #pragma unroll
        for (int r = 0; r < 4; ++r)
            xb[r * Dsz + j] = xf[r];
        __syncthreads();

        if (ch < 31) {
            #pragma unroll
            for (int r = 0; r < 4; ++r)
                xf[r] = x[(size_t)(m0 + (ch + 1) * 4 + r) * Dsz + j];
        }

        unsigned long long a0 = 0ull, a1 = 0ull, a2 = 0ull, a3 = 0ull;
        unsigned long long a4 = 0ull, a5 = 0ull, a6 = 0ull, a7 = 0ull;
        #pragma unroll
        for (int c = 0; c < 32; ++c) {
            ulonglong2 v0 = *(const ulonglong2*)(xb + 0 * Dsz + 4 * c);
            ulonglong2 v1 = *(const ulonglong2*)(xb + 1 * Dsz + 4 * c);
            ulonglong2 v2 = *(const ulonglong2*)(xb + 2 * Dsz + 4 * c);
            ulonglong2 v3 = *(const ulonglong2*)(xb + 3 * Dsz + 4 * c);
            a0 = ffma2(wi[2 * c], v0.x, a0);  a1 = ffma2(wi[2 * c + 1], v0.y, a1);
            a2 = ffma2(wi[2 * c], v1.x, a2);  a3 = ffma2(wi[2 * c + 1], v1.y, a3);
            a4 = ffma2(wi[2 * c], v2.x, a4);  a5 = ffma2(wi[2 * c + 1], v2.y, a5);
            a6 = ffma2(wi[2 * c], v3.x, a6);  a7 = ffma2(wi[2 * c + 1], v3.y, a7);
        }
        const int m = m0 + ch * 4;
        g_xin[(size_t)(m + 0) * Hsz + j] = f2sum(a0) + f2sum(a1) + bi;
        g_xin[(size_t)(m + 1) * Hsz + j] = f2sum(a2) + f2sum(a3) + bi;
        g_xin[(size_t)(m + 2) * Hsz + j] = f2sum(a4) + f2sum(a5) + bi;
        g_xin[(size_t)(m + 3) * Hsz + j] = f2sum(a6) + f2sum(a7) + bi;
    }
}

// ---------------------------------------------------------------------------
// Kernel 2: sequential scan. grid 128 x 256 threads, 4 rows/CTA.
// Thread (p, hf, rp): units j0=2p..2p+1; k in [64*hf, 64*hf+64); rows 2rp, 2rp+1.
// Row-pair groups (warps 0-3 vs 4-7) run in SEPARATE named-barrier domains.
// ---------------------------------------------------------------------------
__global__ void __launch_bounds__(256, 1)
ltc_main(const float* __restrict__ W_r,
         const float* __restrict__ b_r,
         const float* __restrict__ W_fc,
         const float* __restrict__ b_fc,
         float* __restrict__ out)
{
    __shared__ float hs[4][Hsz];           // published hidden state
    __shared__ float part[2][4][Hsz];      // [k-half][row][j] partial dots
    __shared__ float red[4][Hsz];          // final reduction scratch

    const int tid  = threadIdx.x;
    const int p    = tid & 63;             // j-pair index
    const int hf   = (tid >> 6) & 1;       // k-half
    const int rp   = tid >> 7;             // row-pair group (barrier domain)
    const int k0   = hf << 6;
    const int j0   = 2 * p;
    const int jown = tid & 127;            // owned hidden unit
    const int r0   = 2 * rp, r1 = 2 * rp + 1;
    const int base = blockIdx.x * 4;
    const int barid = rp + 1;              // named barrier 1 or 2

    // W_r rows j0, j0+1, columns [k0, k0+64): 128 floats in registers.
    unsigned long long wA[32], wB[32];
    {
        const ulonglong2* wpA = (const ulonglong2*)(W_r + (size_t)j0 * Hsz + k0);
        const ulonglong2* wpB = (const ulonglong2*)(W_r + (size_t)(j0 + 1) * Hsz + k0);
        #pragma unroll
        for (int c = 0; c < 16; ++c) {
            ulonglong2 vA = wpA[c];
            ulonglong2 vB = wpB[c];
            wA[2 * c] = vA.x;  wA[2 * c + 1] = vA.y;
            wB[2 * c] = vB.x;  wB[2 * c + 1] = vB.y;
        }
    }

    const float bb  = b_r[jown];
    const float wfc = W_fc[jown];

    float h0 = 0.f, h1 = 0.f;   // owned: (jown, r0) and (jown, r1)

    const size_t xi0 = (size_t)(base + r0) * Ssz * Hsz + jown;
    const size_t xi1 = (size_t)(base + r1) * Ssz * Hsz + jown;
    float xf0 = g_xin[xi0], xf1 = g_xin[xi1];

    #pragma unroll 1
    for (int t = 0; t < Ssz; ++t) {
        const float xin0 = xf0 + bb, xin1 = xf1 + bb;
        if (t + 1 < Ssz) {
            const size_t o = (size_t)(t + 1) * Hsz;
            xf0 = g_xin[xi0 + o];
            xf1 = g_xin[xi1 + o];
        }

        #pragma unroll 1
        for (int u = 0; u < UNFOLDS; ++u) {
            // 1) publish owned h (group-local)
            hs[r0][jown] = h0;
            hs[r1][jown] = h1;
            group_bar(barid);

            // 2) partial dots: 2 units x 2 rows over this thread's k-half.
            unsigned long long a00 = 0ull, a01 = 0ull, a10 = 0ull, a11 = 0ull;
            unsigned long long b00 = 0ull, b01 = 0ull, b10 = 0ull, b11 = 0ull;
            #pragma unroll          // full unroll: wA/wB must stay in registers
            for (int c = 0; c < 16; ++c) {
                ulonglong2 v0 = *(const ulonglong2*)&hs[r0][k0 + 4 * c];
                ulonglong2 v1 = *(const ulonglong2*)&hs[r1][k0 + 4 * c];
                a00 = ffma2(wA[2 * c], v0.x, a00);  a01 = ffma2(wA[2 * c + 1], v0.y, a01);
                a10 = ffma2(wB[2 * c], v0.x, a10);  a11 = ffma2(wB[2 * c + 1], v0.y, a11);
                b00 = ffma2(wA[2 * c], v1.x, b00);  b01 = ffma2(wA[2 * c + 1], v1.y, b01);
                b10 = ffma2(wB[2 * c], v1.x, b10);  b11 = ffma2(wB[2 * c + 1], v1.y, b11);
            }
            float2 pr0, pr1;
            pr0.x = f2sum(a00) + f2sum(a01);   // (j0,   r0)
            pr0.y = f2sum(a10) + f2sum(a11);   // (j0+1, r0)
            pr1.x = f2sum(b00) + f2sum(b01);   // (j0,   r1)
            pr1.y = f2sum(b10) + f2sum(b11);   // (j0+1, r1)
            *(float2*)&part[hf][r0][j0] = pr0;
            *(float2*)&part[hf][r1][j0] = pr1;
            group_bar(barid);

            // 3) combine halves + nonlinearity on owned states
            const float s0 = part[0][r0][jown] + part[1][r0][jown] + xin0;
            const float s1 = part[0][r1][jown] + part[1][r1][jown] + xin1;
            h0 = 0.9f * h0 + 0.1f * ftanh(s0);
            h1 = 0.9f * h1 + 0.1f * ftanh(s1);
        }
    }

    // out[b] = b_fc + sum_j h[b][j] * W_fc[j]  (full-CTA sync: groups rejoin)
    __syncthreads();
    red[r0][jown] = h0 * wfc;
    red[r1][jown] = h1 * wfc;
    __syncthreads();

    const int wid = tid >> 5, lane = tid & 31;
    if (wid < 4) {
        float4 v = *(const float4*)&red[wid][4 * lane];
        float s = (v.x + v.y) + (v.z + v.w);
        #pragma unroll
        for (int d = 16; d > 0; d >>= 1)
            s += __shfl_xor_sync(0xffffffffu, s, d);
        if (lane == 0)
            out[base + wid] = s + b_fc[0];
    }
}

extern "C" void kernel_launch(void* const* d_in, const int* in_sizes, int n_in,
                              void* d_out, int out_size)
{
    const float* x    = (const float*)d_in[0];
    const float* W_in = (const float*)d_in[1];
    const float* b_in = (const float*)d_in[2];
    const float* W_r  = (const float*)d_in[3];
    const float* b_r  = (const float*)d_in[4];
    const float* W_fc = (const float*)d_in[5];
    const float* b_fc = (const float*)d_in[6];
    float* out = (float*)d_out;

    xin_kernel<<<(Bsz * Ssz) / 128, 128>>>(x, W_in, b_in);
    ltc_main<<<Bsz / 4, 256>>>(W_r, b_r, W_fc, b_fc, out);
}

// round 7
// speedup vs baseline: 1.0391x; 1.0391x over previous
#include <cuda_runtime.h>
#include <cstdint>

// LTC scan, round 7.
// R6 post-mortem: named barriers were neutral — symmetric groups stay
// phase-locked; every unfold still exposes a pure-latency tail (~650cyc over
// the 256cyc FMA floor).
// R7: software-pipeline the two independent row chains (rA, rB) inside each
// row-pair group with a HALF-UNFOLD SKEW. Each barrier interval ("tick") =
// dot(X) [FMA issue work] + tail(Y) [f2sum/tanh/publish latency work], so the
// tanh/combine latency of one chain hides under the FFMA2 stream of the other.
// Bootstrap branchless: partials zero-initialized + dummy xin=0 -> tanh(0)=0.

#define Bsz 512
#define Ssz 512
#define Dsz 128
#define Hsz 128
#define UNFOLDS 6

typedef unsigned long long ull;

__device__ float g_xin[(size_t)Bsz * Ssz * Hsz];   // [b][s][h] scratch

__device__ __forceinline__ ull ffma2(ull a, ull b, ull c) {
    ull d;
    asm("fma.rn.f32x2 %0, %1, %2, %3;" : "=l"(d) : "l"(a), "l"(b), "l"(c));
    return d;
}

__device__ __forceinline__ float f2sum(ull v) {
    float lo, hi;
    asm("mov.b64 {%0, %1}, %2;" : "=f"(lo), "=f"(hi) : "l"(v));
    return lo + hi;
}

__device__ __forceinline__ float ftanh(float s) {
    float e = __expf(2.0f * s);
    return 1.0f - __fdividef(2.0f, e + 1.0f);
}

// ---------------------------------------------------------------------------
// Kernel 1: xin[b,s,j] = sum_d x[b,s,d] * W_in[j,d] + b_in[j]
// ---------------------------------------------------------------------------
__global__ void __launch_bounds__(128, 2)
xin_kernel(const float* __restrict__ x,
           const float* __restrict__ W_in,
           const float* __restrict__ b_in)
{
    __shared__ float xs[2][4 * Dsz];

    const int j = threadIdx.x;

    ull wi[64];
    {
        const ulonglong2* wp = (const ulonglong2*)(W_in + j * Dsz);
        #pragma unroll
        for (int c = 0; c < 32; ++c) {
            ulonglong2 v = wp[c];
            wi[2 * c]     = v.x;
            wi[2 * c + 1] = v.y;
        }
    }
    const float bi = b_in[j];

    const int m0 = blockIdx.x * 128;

    float xf[4];
    #pragma unroll
    for (int r = 0; r < 4; ++r)
        xf[r] = x[(size_t)(m0 + r) * Dsz + j];

    #pragma unroll 1
    for (int ch = 0; ch < 32; ++ch) {
        float* xb = xs[ch & 1];
        #pragma unroll
        for (int r = 0; r < 4; ++r)
            xb[r * Dsz + j] = xf[r];
        __syncthreads();

        if (ch < 31) {
            #pragma unroll
            for (int r = 0; r < 4; ++r)
                xf[r] = x[(size_t)(m0 + (ch + 1) * 4 + r) * Dsz + j];
        }

        ull a0 = 0ull, a1 = 0ull, a2 = 0ull, a3 = 0ull;
        ull a4 = 0ull, a5 = 0ull, a6 = 0ull, a7 = 0ull;
        #pragma unroll
        for (int c = 0; c < 32; ++c) {
            ulonglong2 v0 = *(const ulonglong2*)(xb + 0 * Dsz + 4 * c);
            ulonglong2 v1 = *(const ulonglong2*)(xb + 1 * Dsz + 4 * c);
            ulonglong2 v2 = *(const ulonglong2*)(xb + 2 * Dsz + 4 * c);
            ulonglong2 v3 = *(const ulonglong2*)(xb + 3 * Dsz + 4 * c);
            a0 = ffma2(wi[2 * c], v0.x, a0);  a1 = ffma2(wi[2 * c + 1], v0.y, a1);
            a2 = ffma2(wi[2 * c], v1.x, a2);  a3 = ffma2(wi[2 * c + 1], v1.y, a3);
            a4 = ffma2(wi[2 * c], v2.x, a4);  a5 = ffma2(wi[2 * c + 1], v2.y, a5);
            a6 = ffma2(wi[2 * c], v3.x, a6);  a7 = ffma2(wi[2 * c + 1], v3.y, a7);
        }
        const int m = m0 + ch * 4;
        g_xin[(size_t)(m + 0) * Hsz + j] = f2sum(a0) + f2sum(a1) + bi;
        g_xin[(size_t)(m + 1) * Hsz + j] = f2sum(a2) + f2sum(a3) + bi;
        g_xin[(size_t)(m + 2) * Hsz + j] = f2sum(a4) + f2sum(a5) + bi;
        g_xin[(size_t)(m + 3) * Hsz + j] = f2sum(a6) + f2sum(a7) + bi;
    }
}

// ---------------------------------------------------------------------------
// Kernel 2: skewed-pipeline scan. grid 128 x 256 threads, 4 rows/CTA.
// Thread (p, hf, rp): units j0=2p..2p+1, k-half [64hf,64hf+64), rows 2rp,2rp+1.
// ---------------------------------------------------------------------------
__global__ void __launch_bounds__(256, 1)
ltc_main(const float* __restrict__ W_r,
         const float* __restrict__ b_r,
         const float* __restrict__ W_fc,
         const float* __restrict__ b_fc,
         float* __restrict__ out)
{
    __shared__ float hs[4][Hsz];          // published hidden state per row
    __shared__ float part[2][4][Hsz];     // [k-half][row][j] partial dots
    __shared__ float red[4][Hsz];

    const int tid  = threadIdx.x;
    const int p    = tid & 63;
    const int hf   = (tid >> 6) & 1;
    const int rp   = tid >> 7;
    const int k0   = hf << 6;
    const int j0   = 2 * p;
    const int jown = tid & 127;
    const int rA   = 2 * rp, rB = 2 * rp + 1;
    const int base = blockIdx.x * 4;

    // W_r rows j0, j0+1, cols [k0, k0+64): 128 floats in registers.
    ull wA[32], wB[32];
    {
        const ulonglong2* wpA = (const ulonglong2*)(W_r + (size_t)j0 * Hsz + k0);
        const ulonglong2* wpB = (const ulonglong2*)(W_r + (size_t)(j0 + 1) * Hsz + k0);
        #pragma unroll
        for (int c = 0; c < 16; ++c) {
            ulonglong2 vA = wpA[c];
            ulonglong2 vB = wpB[c];
            wA[2 * c] = vA.x;  wA[2 * c + 1] = vA.y;
            wB[2 * c] = vB.x;  wB[2 * c + 1] = vB.y;
        }
    }

    const float bb  = b_r[jown];
    const float wfc = W_fc[jown];

    float hA = 0.f, hB = 0.f;

    // Bootstrap: publish h=0; zero rB partials so the first (dummy) tail(B)
    // computes tanh(0)=0 and leaves hB=0 — branchless pipeline fill.
    hs[rA][jown] = 0.f;
    hs[rB][jown] = 0.f;
    part[hf][rB][j0]     = 0.f;
    part[hf][rB][j0 + 1] = 0.f;

    const size_t xiA = (size_t)(base + rA) * Ssz * Hsz + jown;
    const size_t xiB = (size_t)(base + rB) * Ssz * Hsz + jown;
    float xfA = g_xin[xiA], xfB = g_xin[xiB];

    float xinB_tail = 0.f;   // dummy xin for the pipeline-fill tail(B)

    // One tick: BAR; tail(Y) [combine+tanh+publish]; dot(X) [FFMA2 burst]+store partials.
    #define TICK(rX, rY, hY, xinY)                                              \
    {                                                                           \
        __syncthreads();                                                        \
        const float pY0 = part[0][rY][jown];                                    \
        const float pY1 = part[1][rY][jown];                                    \
        ull a0 = 0ull, a1 = 0ull, b0 = 0ull, b1 = 0ull;                         \
        _Pragma("unroll")                                                       \
        for (int c = 0; c < 16; ++c) {                                          \
            ulonglong2 v = *(const ulonglong2*)&hs[rX][k0 + 4 * c];             \
            a0 = ffma2(wA[2 * c], v.x, a0);  a1 = ffma2(wA[2 * c + 1], v.y, a1);\
            b0 = ffma2(wB[2 * c], v.x, b0);  b1 = ffma2(wB[2 * c + 1], v.y, b1);\
        }                                                                       \
        hY = 0.9f * hY + 0.1f * ftanh(pY0 + pY1 + (xinY));                      \
        hs[rY][jown] = hY;                                                      \
        float2 pr;                                                              \
        pr.x = f2sum(a0) + f2sum(a1);                                           \
        pr.y = f2sum(b0) + f2sum(b1);                                           \
        *(float2*)&part[hf][rX][j0] = pr;                                       \
    }

    #pragma unroll 1
    for (int t = 0; t < Ssz; ++t) {
        const float xinA = xfA + bb;
        const float xinB = xfB + bb;
        if (t + 1 < Ssz) {
            const size_t o = (size_t)(t + 1) * Hsz;
            xfA = g_xin[xiA + o];
            xfB = g_xin[xiB + o];
        }

        #pragma unroll 1
        for (int u = 0; u < UNFOLDS; ++u) {
            const float xB = (u == 0) ? xinB_tail : xinB;  // u=0 tail is unfold 5 of t-1
            TICK(rA, rB, hB, xB);     // dot A(u), tail B(prev)
            TICK(rB, rA, hA, xinA);   // dot B(u), tail A(u)
        }
        xinB_tail = xinB;
    }

    // Drain: final tail(B) — unfold 5 of t=511.
    __syncthreads();
    {
        const float pY0 = part[0][rB][jown];
        const float pY1 = part[1][rB][jown];
        hB = 0.9f * hB + 0.1f * ftanh(pY0 + pY1 + xinB_tail);
    }

    // out[b] = b_fc + sum_j h[b][j] * W_fc[j]
    __syncthreads();
    red[rA][jown] = hA * wfc;
    red[rB][jown] = hB * wfc;
    __syncthreads();

    const int wid = tid >> 5, lane = tid & 31;
    if (wid < 4) {
        float4 v = *(const float4*)&red[wid][4 * lane];
        float s = (v.x + v.y) + (v.z + v.w);
        #pragma unroll
        for (int d = 16; d > 0; d >>= 1)
            s += __shfl_xor_sync(0xffffffffu, s, d);
        if (lane == 0)
            out[base + wid] = s + b_fc[0];
    }
    #undef TICK
}

extern "C" void kernel_launch(void* const* d_in, const int* in_sizes, int n_in,
                              void* d_out, int out_size)
{
    const float* x    = (const float*)d_in[0];
    const float* W_in = (const float*)d_in[1];
    const float* b_in = (const float*)d_in[2];
    const float* W_r  = (const float*)d_in[3];
    const float* b_r  = (const float*)d_in[4];
    const float* W_fc = (const float*)d_in[5];
    const float* b_fc = (const float*)d_in[6];
    float* out = (float*)d_out;

    xin_kernel<<<(Bsz * Ssz) / 128, 128>>>(x, W_in, b_in);
    ltc_main<<<Bsz / 4, 256>>>(W_r, b_r, W_fc, b_fc, out);
}